// round 11
// baseline (speedup 1.0000x reference)
#include <cuda_runtime.h>

#define KPTS    16384
#define NATOMS  1024
#define NB      16
#define NSRC    17      // source 0 = C, sources 1..16 = C1[b]
#define NC      5       // cells per axis (h = 2.0)
#define NCELLS  125
#define NSLICE  16      // dom binning slices (1024 points each)
#define SLCAP   40      // dom points per (cell, slice) capacity (mean 8.2)
#define ACAP    40      // atoms per (source, cell) capacity (mean 8.2)
#define DCAP    640     // max dom points per cell
#define SCAP    448     // gathered 27-cell atom capacity (mean 221)
#define SUBPAIR 72      // pairs per subcell list (144 atoms; mean 90, >5 sigma)
#define SUBSTG  146     // staging slots per subcell (2*SUBPAIR + pad)
#define RSLICE  64      // reduction slices (256 points each)

// L = inv2s * log2(e) = 2*pi * 1.4426950408889634
#define LCONST  9.064720283654388f
#define INV2L   (1.0f / (2.0f * LCONST))

typedef unsigned long long u64;

// static scratch (no allocations allowed)
__device__ float4     g_binned[NSRC * NCELLS * ACAP];
__device__ int        g_acount[NSRC * NCELLS];
__device__ int        g_dslice[NCELLS * NSLICE * SLCAP];
__device__ int        g_dcnt2[NCELLS * NSLICE];
__device__ float4     g_kcoef[KPTS];
__device__ ulonglong2 g_pairsA[(size_t)NSRC * NCELLS * 8 * SUBPAIR]; // (x0,x1),(y0,y1)
__device__ ulonglong2 g_pairsB[(size_t)NSRC * NCELLS * 8 * SUBPAIR]; // (z0,z1),(w0,w1)
__device__ int        g_pcnt[NSRC * NCELLS * 8];     // pair count per subcell list
__device__ int        g_kidx[NCELLS * DCAP];         // point id | (subcell << 16)
__device__ float4     g_kc[NCELLS * DCAP];           // grouped kcoefs
__device__ int        g_dcountc[NCELLS];
__device__ float      g_theta[NSRC * KPTS];
__device__ float      g_partial[NB * RSLICE];

__device__ __forceinline__ int cell_of(float x, float y, float z) {
    int cx = min(NC - 1, max(0, (int)(x * 0.5f)));
    int cy = min(NC - 1, max(0, (int)(y * 0.5f)));
    int cz = min(NC - 1, max(0, (int)(z * 0.5f)));
    return (cz * NC + cy) * NC + cx;
}

// ---- packed f32x2 helpers --------------------------------------------------
__device__ __forceinline__ u64 pk2(float lo, float hi) {
    u64 r; asm("mov.b64 %0, {%1, %2};" : "=l"(r) : "f"(lo), "f"(hi)); return r;
}
__device__ __forceinline__ void upk2(u64 v, float& lo, float& hi) {
    asm("mov.b64 {%0, %1}, %2;" : "=f"(lo), "=f"(hi) : "l"(v));
}
__device__ __forceinline__ u64 fma2(u64 a, u64 b, u64 c) {
    u64 r; asm("fma.rn.f32x2 %0, %1, %2, %3;" : "=l"(r) : "l"(a), "l"(b), "l"(c)); return r;
}
__device__ __forceinline__ u64 add2(u64 a, u64 b) {
    u64 r; asm("add.rn.f32x2 %0, %1, %2;" : "=l"(r) : "l"(a), "l"(b)); return r;
}
__device__ __forceinline__ float ex2(float a) {
    float e; asm("ex2.approx.ftz.f32 %0, %1;" : "=f"(e) : "f"(a)); return e;
}

// ---------------------------------------------------------------------------
// prep1: 33 blocks x 1024 threads.
// Blocks 0..15: dom binning by 1024-point slice. Single atomic round with
//   match-aggregated smem atomics (one atomic per distinct cell per warp).
//   Slot order is FP-irrelevant (each point's theta goes to its own index and
//   the final dot sums in fixed order). Also writes per-point kcoef.
// Blocks 16..32: deterministic atom binning (atom index order preserved).
// ---------------------------------------------------------------------------
__global__ void __launch_bounds__(1024) prep1_kernel(const float* __restrict__ C1,
                                                     const float* __restrict__ C,
                                                     const float* __restrict__ dom) {
    const int tid = threadIdx.x;
    const int bid = blockIdx.x;
    const int lane = tid & 31;

    if (bid < NSLICE) {
        __shared__ int hist[NCELLS];
        if (tid < NCELLS) hist[tid] = 0;
        const int k = bid * 1024 + tid;
        const float x = dom[k * 3 + 0];
        const float y = dom[k * 3 + 1];
        const float z = dom[k * 3 + 2];
        g_kcoef[k] = make_float4(x, y, z, -LCONST * (x * x + y * y + z * z));
        const int c = cell_of(x, y, z);
        __syncthreads();
        unsigned mm   = __match_any_sync(0xffffffffu, c);
        int      lead = __ffs(mm) - 1;
        int      rank = __popc(mm & ((1u << lane) - 1u));
        int base = 0;
        if (lane == lead) base = atomicAdd(&hist[c], __popc(mm));
        base = __shfl_sync(0xffffffffu, base, lead);
        int slot = base + rank;
        if (slot < SLCAP) g_dslice[(c * NSLICE + bid) * SLCAP + slot] = k;
        __syncthreads();
        if (tid < NCELLS) g_dcnt2[tid * NSLICE + bid] = min(hist[tid], SLCAP);
    } else {
        __shared__ int wcnt[32 * 128];           // [warp][cell]
        const int s = bid - NSLICE;
        const float* src = (s == 0) ? C : (C1 + (size_t)(s - 1) * NATOMS * 3);
        const int w = tid >> 5;

        #pragma unroll
        for (int i = 0; i < 4; ++i) wcnt[tid + i * 1024] = 0;

        const float x = src[tid * 3 + 0];
        const float y = src[tid * 3 + 1];
        const float z = src[tid * 3 + 2];
        const int   c = cell_of(x, y, z);
        __syncthreads();

        unsigned mm  = __match_any_sync(0xffffffffu, c);
        int     rank = __popc(mm & ((1u << lane) - 1u));
        if (rank == 0) wcnt[w * 128 + c] = __popc(mm);
        __syncthreads();

        if (tid < NCELLS) {
            int acc = 0;
            #pragma unroll
            for (int ww = 0; ww < 32; ++ww) {
                int v = wcnt[ww * 128 + tid];
                wcnt[ww * 128 + tid] = acc;       // exclusive warp base
                acc += v;
            }
            g_acount[s * NCELLS + tid] = min(acc, ACAP);
        }
        __syncthreads();

        int pos = wcnt[w * 128 + c] + rank;
        if (pos < ACAP) {
            float phi = x * x + y * y + z * z;
            g_binned[(s * NCELLS + c) * ACAP + pos] =
                make_float4(2.f * LCONST * x, 2.f * LCONST * y,
                            2.f * LCONST * z, -LCONST * phi);
        }
    }
}

// ---------------------------------------------------------------------------
// prep2: grid (125, 17) x 256 threads. Per (cell, source):
//   gather 27-cell neighbor atoms (deterministic order), then WARP w prunes
//   SUBCELL w (h=1 cube): keep atoms within distance 2.0 of the subcube
//   (dropped terms < 2^-36 each). 8 subcell pair lists written to global.
// s==0 blocks additionally stitch the cell's dom points grouped BY SUBCELL
//   into contiguous (idx|sub<<16, kcoef) arrays.
// ---------------------------------------------------------------------------
__global__ void __launch_bounds__(256) prep2_kernel() {
    __shared__ float4 satoms[SCAP];
    __shared__ float4 stage[8][SUBSTG];
    __shared__ int    ncl[27], scnt[27];
    const int cell = blockIdx.x;
    const int s    = blockIdx.y;
    const int tid  = threadIdx.x;
    const int lane = tid & 31;
    const int w    = tid >> 5;
    const int cx = cell % NC, cy = (cell / NC) % NC, cz = cell / (NC * NC);

    if (tid < 27) {
        int dx = tid % 3 - 1, dy = (tid / 3) % 3 - 1, dz = tid / 9 - 1;
        int nx = cx + dx, ny = cy + dy, nz = cz + dz;
        bool ok = (unsigned)nx < NC && (unsigned)ny < NC && (unsigned)nz < NC;
        int nc2 = ok ? (nz * NC + ny) * NC + nx : -1;
        ncl[tid]  = nc2;
        scnt[tid] = ok ? g_acount[s * NCELLS + nc2] : 0;
    }
    __syncthreads();

    // gather (uniform traversal, deterministic order)
    int base = 0;
    #pragma unroll 1
    for (int ci = 0; ci < 27; ++ci) {
        int cnt = scnt[ci];
        if (cnt) {
            const float4* srcp = g_binned + (s * NCELLS + ncl[ci]) * ACAP;
            for (int i = tid; i < cnt; i += 256) {
                int pos = base + i;
                if (pos < SCAP) satoms[pos] = srcp[i];
            }
            base += cnt;
        }
    }
    const int ntot = min(base, SCAP);
    __syncthreads();

    // warp w prunes subcell w (deterministic ballot compaction into staging)
    {
        const float lox = 2.f * cx + (float)(w & 1);
        const float loy = 2.f * cy + (float)((w >> 1) & 1);
        const float loz = 2.f * cz + (float)(w >> 2);
        int nk = 0;
        for (int i0 = 0; i0 < ntot; i0 += 32) {
            int i = i0 + lane;
            bool keep = false;
            float4 a;
            if (i < ntot) {
                a = satoms[i];
                float x = a.x * INV2L, y = a.y * INV2L, z = a.z * INV2L;
                float dx = fmaxf(fmaxf(lox - x, x - (lox + 1.f)), 0.f);
                float dy = fmaxf(fmaxf(loy - y, y - (loy + 1.f)), 0.f);
                float dz = fmaxf(fmaxf(loz - z, z - (loz + 1.f)), 0.f);
                keep = fmaf(dx, dx, fmaf(dy, dy, dz * dz)) <= 4.0f;
            }
            unsigned m = __ballot_sync(0xffffffffu, keep);
            if (keep) {
                int pos = nk + __popc(m & ((1u << lane) - 1u));
                if (pos < 2 * SUBPAIR) stage[w][pos] = a;
            }
            nk += __popc(m);
        }
        nk = min(nk, 2 * SUBPAIR);
        if (lane == 0 && (nk & 1)) stage[w][nk] = make_float4(0.f, 0.f, 0.f, -1e30f);
        __syncwarp();
        const int np = (nk + 1) >> 1;
        ulonglong2* gA = g_pairsA + ((size_t)(s * NCELLS + cell) * 8 + w) * SUBPAIR;
        ulonglong2* gB = g_pairsB + ((size_t)(s * NCELLS + cell) * 8 + w) * SUBPAIR;
        for (int jp = lane; jp < np; jp += 32) {
            float4 a = stage[w][2 * jp];
            float4 b = stage[w][2 * jp + 1];
            gA[jp] = make_ulonglong2(pk2(a.x, b.x), pk2(a.y, b.y));
            gB[jp] = make_ulonglong2(pk2(a.z, b.z), pk2(a.w, b.w));
        }
        if (lane == 0) g_pcnt[(s * NCELLS + cell) * 8 + w] = np;
    }

    if (s == 0) {
        // stitch dom points grouped by subcell (slot order FP-irrelevant)
        __shared__ int cnt16[NSLICE], pcnt[8], poff[9];
        if (tid < NSLICE) cnt16[tid] = g_dcnt2[cell * NSLICE + tid];
        if (tid < 8) pcnt[tid] = 0;
        __syncthreads();
        int    kk[3], su[3], sl[3];
        float4 kcv[3];
        int nmine = 0;
        for (int idx = tid; idx < NSLICE * SLCAP; idx += 256) {
            int slc = idx / SLCAP, j = idx % SLCAP;
            if (j < cnt16[slc]) {
                int k = g_dslice[(cell * NSLICE + slc) * SLCAP + j];
                float4 kc = g_kcoef[k];
                int sx = min(1, max(0, (int)kc.x - 2 * cx));
                int sy = min(1, max(0, (int)kc.y - 2 * cy));
                int sz = min(1, max(0, (int)kc.z - 2 * cz));
                int sub = (sz << 2) | (sy << 1) | sx;
                kk[nmine]  = k;
                su[nmine]  = sub;
                sl[nmine]  = atomicAdd(&pcnt[sub], 1);
                kcv[nmine] = kc;
                ++nmine;
            }
        }
        __syncthreads();
        if (tid == 0) {
            int a = 0;
            #pragma unroll
            for (int i = 0; i < 8; ++i) { poff[i] = a; a += pcnt[i]; }
            poff[8] = a;
            g_dcountc[cell] = a;
        }
        __syncthreads();
        for (int i = 0; i < nmine; ++i) {
            int pos = poff[su[i]] + sl[i];
            g_kidx[cell * DCAP + pos] = kk[i] | (su[i] << 16);
            g_kc[cell * DCAP + pos]   = kcv[i];
        }
    }
}

// ---------------------------------------------------------------------------
// theta: grid (125, 17) x 160 threads. Loads the 8 subcell pair lists into
// contiguous smem, then each point loops only over its subcell's list
// (~45 pairs instead of ~85). Deterministic summation order.
// ---------------------------------------------------------------------------
__global__ void __launch_bounds__(160) theta_kernel() {
    __shared__ ulonglong2 sA[8 * SUBPAIR];
    __shared__ ulonglong2 sB[8 * SUBPAIR];
    __shared__ int scnt2[8], soff2[9];
    const int cell = blockIdx.x;
    const int s    = blockIdx.y;
    const int tid  = threadIdx.x;

    if (tid < 8) scnt2[tid] = g_pcnt[(s * NCELLS + cell) * 8 + tid];
    __syncthreads();
    if (tid == 0) {
        int a = 0;
        #pragma unroll
        for (int i = 0; i < 8; ++i) { soff2[i] = a; a += scnt2[i]; }
        soff2[8] = a;
    }
    __syncthreads();

    #pragma unroll 1
    for (int sub = 0; sub < 8; ++sub) {
        const int cnt = scnt2[sub], off = soff2[sub];
        const ulonglong2* gA = g_pairsA + ((size_t)(s * NCELLS + cell) * 8 + sub) * SUBPAIR;
        const ulonglong2* gB = g_pairsB + ((size_t)(s * NCELLS + cell) * 8 + sub) * SUBPAIR;
        for (int i = tid; i < cnt; i += 160) {
            sA[off + i] = gA[i];
            sB[off + i] = gB[i];
        }
    }
    __syncthreads();

    const int npts = g_dcountc[cell];
    for (int p = tid; p < npts; p += 160) {
        const int pk  = g_kidx[cell * DCAP + p];
        const int sub = pk >> 16;
        const int idx = pk & 0xFFFF;
        const float4 kc = g_kc[cell * DCAP + p];
        const u64 kx2 = pk2(kc.x, kc.x);
        const u64 ky2 = pk2(kc.y, kc.y);
        const u64 kz2 = pk2(kc.z, kc.z);
        const u64 kw2 = pk2(kc.w, kc.w);
        const int jbeg = soff2[sub];
        const int jend = jbeg + scnt2[sub];
        u64 acc = 0ull;
        #pragma unroll 4
        for (int jp = jbeg; jp < jend; ++jp) {
            ulonglong2 A = sA[jp];
            ulonglong2 B = sB[jp];
            u64 t = add2(B.y, kw2);
            t = fma2(kz2, B.x, t);
            t = fma2(ky2, A.y, t);
            t = fma2(kx2, A.x, t);
            float lo, hi; upk2(t, lo, hi);
            acc = add2(acc, pk2(ex2(lo), ex2(hi)));
        }
        float a0, a1; upk2(acc, a0, a1);
        g_theta[s * KPTS + idx] = a0 + a1;
    }
}

// ---------------------------------------------------------------------------
// Reduction stage A: grid (NB, RSLICE) x 128 threads. Block (b, j) dots the
// 256-point slice j of theta[b+1] . theta[0]. Fixed tree -> deterministic.
// ---------------------------------------------------------------------------
__global__ void __launch_bounds__(128) reduceA_kernel() {
    __shared__ float red[4];
    const int b = blockIdx.x, j = blockIdx.y;
    const int tid = threadIdx.x, lane = tid & 31, w = tid >> 5;
    const float* tb = g_theta + (size_t)(1 + b) * KPTS + j * 256;
    const float* t0 = g_theta + j * 256;

    float p = tb[tid] * t0[tid] + tb[tid + 128] * t0[tid + 128];
    #pragma unroll
    for (int st = 16; st > 0; st >>= 1)
        p += __shfl_down_sync(0xffffffffu, p, st);
    if (lane == 0) red[w] = p;
    __syncthreads();
    if (tid == 0)
        g_partial[b * RSLICE + j] = (red[0] + red[1]) + (red[2] + red[3]);
}

// ---------------------------------------------------------------------------
// Reduction stage B: 1 block x 256 threads. 16 threads per b fold the 64
// partials. out[b] = 1 - clip(scale * dot, 0, 1),
// scale = A*V/sqrt(n1*n2) = 8 * (1000/16384) / 1024.
// ---------------------------------------------------------------------------
__global__ void __launch_bounds__(256) reduceB_kernel(float* __restrict__ out) {
    __shared__ float sp[NB][16];
    const int tid = threadIdx.x;
    const int b = tid >> 4, j = tid & 15;
    float a = 0.f;
    #pragma unroll
    for (int i = 0; i < 4; ++i) a += g_partial[b * RSLICE + j + 16 * i];
    sp[b][j] = a;
    __syncthreads();
    #pragma unroll
    for (int st = 8; st > 0; st >>= 1) {
        if (j < st) sp[b][j] += sp[b][j + st];
        __syncthreads();
    }
    if (j == 0) {
        float dot = 4.76837158203125e-4f * sp[b][0];
        dot = fminf(fmaxf(dot, 0.f), 1.f);
        out[b] = 1.f - dot;
    }
}

extern "C" void kernel_launch(void* const* d_in, const int* in_sizes, int n_in,
                              void* d_out, int out_size) {
    const float* C1  = (const float*)d_in[0];   // (16, 1024, 3)
    const float* C   = (const float*)d_in[1];   // (1024, 3)
    const float* dom = (const float*)d_in[2];   // (16384, 3)

    prep1_kernel<<<NSLICE + NSRC, 1024>>>(C1, C, dom);
    prep2_kernel<<<dim3(NCELLS, NSRC), 256>>>();
    theta_kernel<<<dim3(NCELLS, NSRC), 160>>>();
    reduceA_kernel<<<dim3(NB, RSLICE), 128>>>();
    reduceB_kernel<<<1, 256>>>((float*)d_out);
}

// round 12
// speedup vs baseline: 1.5154x; 1.5154x over previous
#include <cuda_runtime.h>

#define KPTS    16384
#define NATOMS  1024
#define NB      16
#define NSRC    17      // source 0 = C, sources 1..16 = C1[b]
#define NC      5       // cells per axis (h = 2.0)
#define NCELLS  125
#define NSLICE  16      // dom binning slices (1024 points each)
#define SLCAP   40      // dom points per (cell, slice) capacity (mean 8.2)
#define ACAP    40      // atoms per (source, cell) capacity (mean 8.2)
#define DCAP    640     // max dom points per cell (16*40)
#define SCAP    448     // gathered neighbor-atom capacity (mean 221)
#define NPAIR   (SCAP / 2)

// L = inv2s * log2(e) = 2*pi * 1.4426950408889634
#define LCONST  9.064720283654388f
#define INV2L   (1.0f / (2.0f * LCONST))

typedef unsigned long long u64;

// static scratch (no allocations allowed)
__device__ float4     g_binned[NSRC * NCELLS * ACAP];
__device__ int        g_acount[NSRC * NCELLS];
__device__ int        g_dslice[NCELLS * NSLICE * SLCAP];
__device__ int        g_dcnt2[NCELLS * NSLICE];
__device__ float4     g_kcoef[KPTS];
__device__ ulonglong2 g_pairsA[NSRC * NCELLS * NPAIR];  // (x0,x1),(y0,y1)
__device__ ulonglong2 g_pairsB[NSRC * NCELLS * NPAIR];  // (z0,z1),(w0,w1)
__device__ int        g_pcount[NSRC * NCELLS];          // pair counts
__device__ int        g_kidx[NCELLS * DCAP];            // stitched point ids
__device__ float4     g_kc[NCELLS * DCAP];              // stitched kcoefs
__device__ int        g_dcountc[NCELLS];
__device__ float      g_theta[NSRC * KPTS];

__device__ __forceinline__ int cell_of(float x, float y, float z) {
    int cx = min(NC - 1, max(0, (int)(x * 0.5f)));
    int cy = min(NC - 1, max(0, (int)(y * 0.5f)));
    int cz = min(NC - 1, max(0, (int)(z * 0.5f)));
    return (cz * NC + cy) * NC + cx;
}

// ---- packed f32x2 helpers --------------------------------------------------
__device__ __forceinline__ u64 pk2(float lo, float hi) {
    u64 r; asm("mov.b64 %0, {%1, %2};" : "=l"(r) : "f"(lo), "f"(hi)); return r;
}
__device__ __forceinline__ void upk2(u64 v, float& lo, float& hi) {
    asm("mov.b64 {%0, %1}, %2;" : "=f"(lo), "=f"(hi) : "l"(v));
}
__device__ __forceinline__ u64 fma2(u64 a, u64 b, u64 c) {
    u64 r; asm("fma.rn.f32x2 %0, %1, %2, %3;" : "=l"(r) : "l"(a), "l"(b), "l"(c)); return r;
}
__device__ __forceinline__ u64 add2(u64 a, u64 b) {
    u64 r; asm("add.rn.f32x2 %0, %1, %2;" : "=l"(r) : "l"(a), "l"(b)); return r;
}
__device__ __forceinline__ float ex2(float a) {
    float e; asm("ex2.approx.ftz.f32 %0, %1;" : "=f"(e) : "f"(a)); return e;
}

// ---------------------------------------------------------------------------
// prep1: 33 blocks x 1024 threads.
// Blocks 0..15: dom binning by 1024-point slice (slot order from smem atomics
//   is FP-irrelevant: each point's theta goes to its own index and the final
//   dot is summed in fixed k order). Also writes per-point kcoef.
// Blocks 16..32: deterministic atom binning (atom index order preserved).
// ---------------------------------------------------------------------------
__global__ void __launch_bounds__(1024) prep1_kernel(const float* __restrict__ C1,
                                                     const float* __restrict__ C,
                                                     const float* __restrict__ dom) {
    const int tid = threadIdx.x;
    const int bid = blockIdx.x;

    if (bid < NSLICE) {
        __shared__ int hist[NCELLS];
        if (tid < NCELLS) hist[tid] = 0;
        const int k = bid * 1024 + tid;
        const float x = dom[k * 3 + 0];
        const float y = dom[k * 3 + 1];
        const float z = dom[k * 3 + 2];
        g_kcoef[k] = make_float4(x, y, z, -LCONST * (x * x + y * y + z * z));
        const int c = cell_of(x, y, z);
        __syncthreads();
        int slot = atomicAdd(&hist[c], 1);
        if (slot < SLCAP) g_dslice[(c * NSLICE + bid) * SLCAP + slot] = k;
        __syncthreads();
        if (tid < NCELLS) g_dcnt2[tid * NSLICE + bid] = min(hist[tid], SLCAP);
    } else {
        __shared__ int wcnt[32 * 128];           // [warp][cell]
        const int s = bid - NSLICE;
        const float* src = (s == 0) ? C : (C1 + (size_t)(s - 1) * NATOMS * 3);
        const int lane = tid & 31;
        const int w    = tid >> 5;

        #pragma unroll
        for (int i = 0; i < 4; ++i) wcnt[tid + i * 1024] = 0;

        const float x = src[tid * 3 + 0];
        const float y = src[tid * 3 + 1];
        const float z = src[tid * 3 + 2];
        const int   c = cell_of(x, y, z);
        __syncthreads();

        unsigned mm  = __match_any_sync(0xffffffffu, c);
        int     rank = __popc(mm & ((1u << lane) - 1u));
        if (rank == 0) wcnt[w * 128 + c] = __popc(mm);
        __syncthreads();

        if (tid < NCELLS) {
            int acc = 0;
            #pragma unroll
            for (int ww = 0; ww < 32; ++ww) {
                int v = wcnt[ww * 128 + tid];
                wcnt[ww * 128 + tid] = acc;       // exclusive warp base
                acc += v;
            }
            g_acount[s * NCELLS + tid] = min(acc, ACAP);
        }
        __syncthreads();

        int pos = wcnt[w * 128 + c] + rank;
        if (pos < ACAP) {
            float phi = x * x + y * y + z * z;
            g_binned[(s * NCELLS + c) * ACAP + pos] =
                make_float4(2.f * LCONST * x, 2.f * LCONST * y,
                            2.f * LCONST * z, -LCONST * phi);
        }
    }
}

// ---------------------------------------------------------------------------
// prep2: grid (125, 17) x 128 threads. Per (cell, source):
//   gather 27-cell neighbor atoms (deterministic order), prune to atoms
//   within distance 2.0 of the home cell cube (dropped terms < 2^-36 each),
//   pack into f32x2 pairs, write to global pair lists.
// Blocks with s==0 additionally stitch the cell's dom points into contiguous
//   (idx, kcoef) arrays so theta reads them with zero preamble.
// ---------------------------------------------------------------------------
__global__ void __launch_bounds__(128) prep2_kernel() {
    __shared__ float4 satoms[SCAP + 1];
    __shared__ int    ncl[27], scnt[27];
    __shared__ int    sNk;
    const int cell = blockIdx.x;
    const int s    = blockIdx.y;
    const int tid  = threadIdx.x;
    const int lane = tid & 31;
    const int cx = cell % NC, cy = (cell / NC) % NC, cz = cell / (NC * NC);

    if (tid < 27) {
        int dx = tid % 3 - 1, dy = (tid / 3) % 3 - 1, dz = tid / 9 - 1;
        int nx = cx + dx, ny = cy + dy, nz = cz + dz;
        bool ok = (unsigned)nx < NC && (unsigned)ny < NC && (unsigned)nz < NC;
        int nc2 = ok ? (nz * NC + ny) * NC + nx : -1;
        ncl[tid]  = nc2;
        scnt[tid] = ok ? g_acount[s * NCELLS + nc2] : 0;
    }
    __syncthreads();

    // gather (uniform traversal, deterministic order)
    int base = 0;
    #pragma unroll 1
    for (int ci = 0; ci < 27; ++ci) {
        int cnt = scnt[ci];
        if (cnt) {
            const float4* srcp = g_binned + (s * NCELLS + ncl[ci]) * ACAP;
            for (int i = tid; i < cnt; i += 128) {
                int pos = base + i;
                if (pos < SCAP) satoms[pos] = srcp[i];
            }
            base += cnt;
        }
    }
    const int ntot = min(base, SCAP);
    __syncthreads();

    // prune (warp 0, deterministic in-place ballot compaction)
    if (tid < 32) {
        const float lox = cx * 2.f, hix = lox + 2.f;
        const float loy = cy * 2.f, hiy = loy + 2.f;
        const float loz = cz * 2.f, hiz = loz + 2.f;
        int nk = 0;
        for (int i0 = 0; i0 < ntot; i0 += 32) {
            int i = i0 + lane;
            bool keep = false;
            float4 a;
            if (i < ntot) {
                a = satoms[i];
                float x = a.x * INV2L, y = a.y * INV2L, z = a.z * INV2L;
                float dx = fmaxf(fmaxf(lox - x, x - hix), 0.f);
                float dy = fmaxf(fmaxf(loy - y, y - hiy), 0.f);
                float dz = fmaxf(fmaxf(loz - z, z - hiz), 0.f);
                keep = fmaf(dx, dx, fmaf(dy, dy, dz * dz)) <= 4.0f;
            }
            unsigned m = __ballot_sync(0xffffffffu, keep);
            __syncwarp();
            if (keep) satoms[nk + __popc(m & ((1u << lane) - 1u))] = a;
            nk += __popc(m);
        }
        if (lane == 0) {
            if (nk & 1) satoms[nk] = make_float4(0.f, 0.f, 0.f, -1e30f);
            sNk = nk;
        }
    }
    __syncthreads();

    const int npairs = (sNk + 1) >> 1;
    ulonglong2* gA = g_pairsA + (size_t)(s * NCELLS + cell) * NPAIR;
    ulonglong2* gB = g_pairsB + (size_t)(s * NCELLS + cell) * NPAIR;
    for (int jp = tid; jp < npairs; jp += 128) {
        float4 a = satoms[2 * jp];
        float4 b = satoms[2 * jp + 1];
        gA[jp] = make_ulonglong2(pk2(a.x, b.x), pk2(a.y, b.y));
        gB[jp] = make_ulonglong2(pk2(a.z, b.z), pk2(a.w, b.w));
    }
    if (tid == 0) g_pcount[s * NCELLS + cell] = npairs;

    if (s == 0) {
        // stitch this cell's dom points into contiguous (idx, kcoef) arrays
        __shared__ int scnt16[NSLICE], soff16[NSLICE + 1];
        if (tid < NSLICE) scnt16[tid] = g_dcnt2[cell * NSLICE + tid];
        __syncthreads();
        if (tid == 0) {
            int a = 0;
            #pragma unroll
            for (int i = 0; i < NSLICE; ++i) { soff16[i] = a; a += scnt16[i]; }
            soff16[NSLICE] = a;
            g_dcountc[cell] = a;
        }
        __syncthreads();
        for (int idx = tid; idx < NSLICE * SLCAP; idx += 128) {
            int sl = idx / SLCAP, j = idx % SLCAP;
            if (j < scnt16[sl]) {
                int k = g_dslice[(cell * NSLICE + sl) * SLCAP + j];
                int pos = soff16[sl] + j;
                g_kidx[cell * DCAP + pos] = k;
                g_kc[cell * DCAP + pos]   = g_kcoef[k];
            }
        }
    }
}

// ---------------------------------------------------------------------------
// theta: grid (125, 17) x 160 threads, smem = pair buffer only (~7.2 KB).
// Preamble is a strided copy of the packed pair list + one sync; inner loop
// is the MUFU-bound f32x2 chain. Deterministic summation order.
// ---------------------------------------------------------------------------
__global__ void __launch_bounds__(160) theta_kernel() {
    __shared__ ulonglong2 sA[NPAIR];
    __shared__ ulonglong2 sB[NPAIR];
    const int cell = blockIdx.x;
    const int s    = blockIdx.y;
    const int tid  = threadIdx.x;

    const int npairs = g_pcount[s * NCELLS + cell];
    const int npts   = g_dcountc[cell];
    const ulonglong2* gA = g_pairsA + (size_t)(s * NCELLS + cell) * NPAIR;
    const ulonglong2* gB = g_pairsB + (size_t)(s * NCELLS + cell) * NPAIR;
    for (int i = tid; i < npairs; i += 160) {
        sA[i] = gA[i];
        sB[i] = gB[i];
    }
    __syncthreads();

    for (int p = tid; p < npts; p += 160) {
        const int idx = g_kidx[cell * DCAP + p];
        const float4 kc = g_kc[cell * DCAP + p];
        const u64 kx2 = pk2(kc.x, kc.x);
        const u64 ky2 = pk2(kc.y, kc.y);
        const u64 kz2 = pk2(kc.z, kc.z);
        const u64 kw2 = pk2(kc.w, kc.w);
        u64 acc = 0ull;
        #pragma unroll 4
        for (int jp = 0; jp < npairs; ++jp) {
            ulonglong2 A = sA[jp];
            ulonglong2 B = sB[jp];
            u64 t = add2(B.y, kw2);
            t = fma2(kz2, B.x, t);
            t = fma2(ky2, A.y, t);
            t = fma2(kx2, A.x, t);
            float lo, hi; upk2(t, lo, hi);
            acc = add2(acc, pk2(ex2(lo), ex2(hi)));
        }
        float a0, a1; upk2(acc, a0, a1);
        g_theta[s * KPTS + idx] = a0 + a1;
    }
}

// ---------------------------------------------------------------------------
// Single-launch reduction: 16 blocks x 1024 threads, one block per output b.
// Each thread accumulates 16 elements via float4 loads (8 independent
// LDG.128 -> latency hidden), then fixed-order warp shuffle + smem tree.
// out[b] = 1 - clip(scale * dot, 0, 1),
// scale = A*V/sqrt(n1*n2) = 8 * (1000/16384) / 1024.
// ---------------------------------------------------------------------------
__global__ void __launch_bounds__(1024) reduce_kernel(float* __restrict__ out) {
    __shared__ float red[32];
    const int b = blockIdx.x;
    const int tid = threadIdx.x, lane = tid & 31, w = tid >> 5;
    const float4* tb = (const float4*)(g_theta + (size_t)(1 + b) * KPTS);
    const float4* t0 = (const float4*)g_theta;

    float p = 0.f;
    #pragma unroll
    for (int i = 0; i < 4; ++i) {
        float4 a = tb[i * 1024 + tid];
        float4 c = t0[i * 1024 + tid];
        p += a.x * c.x + a.y * c.y + a.z * c.z + a.w * c.w;
    }
    #pragma unroll
    for (int st = 16; st > 0; st >>= 1)
        p += __shfl_down_sync(0xffffffffu, p, st);
    if (lane == 0) red[w] = p;
    __syncthreads();
    if (w == 0) {
        float a = red[lane];
        #pragma unroll
        for (int st = 16; st > 0; st >>= 1)
            a += __shfl_down_sync(0xffffffffu, a, st);
        if (lane == 0) {
            float dot = 4.76837158203125e-4f * a;
            dot = fminf(fmaxf(dot, 0.f), 1.f);
            out[b] = 1.f - dot;
        }
    }
}

extern "C" void kernel_launch(void* const* d_in, const int* in_sizes, int n_in,
                              void* d_out, int out_size) {
    const float* C1  = (const float*)d_in[0];   // (16, 1024, 3)
    const float* C   = (const float*)d_in[1];   // (1024, 3)
    const float* dom = (const float*)d_in[2];   // (16384, 3)

    prep1_kernel<<<NSLICE + NSRC, 1024>>>(C1, C, dom);
    prep2_kernel<<<dim3(NCELLS, NSRC), 128>>>();
    theta_kernel<<<dim3(NCELLS, NSRC), 160>>>();
    reduce_kernel<<<NB, 1024>>>((float*)d_out);
}

// round 13
// speedup vs baseline: 1.5543x; 1.0257x over previous
#include <cuda_runtime.h>

#define KPTS    16384
#define NATOMS  1024
#define NB      16
#define NSRC    17      // source 0 = C, sources 1..16 = C1[b]
#define NC      5       // cells per axis (h = 2.0)
#define NCELLS  125
#define NSLICE  16      // dom binning slices (1024 points each)
#define SLCAP   40      // dom points per (cell, slice) capacity (mean 8.2)
#define DCAP    640     // max dom points per cell (16*40)
#define SCAP    448     // pruned atom capacity per cell (mean ~169)
#define NPAIR   (SCAP / 2)

// L = inv2s * log2(e) = 2*pi * 1.4426950408889634
#define LCONST  9.064720283654388f

typedef unsigned long long u64;

// static scratch (no allocations allowed)
__device__ int        g_dslice[NCELLS * NSLICE * SLCAP];
__device__ int        g_dcnt2[NCELLS * NSLICE];
__device__ float4     g_kcoef[KPTS];
__device__ ulonglong2 g_pairsA[NSRC * NCELLS * NPAIR];  // (x0,x1),(y0,y1)
__device__ ulonglong2 g_pairsB[NSRC * NCELLS * NPAIR];  // (z0,z1),(w0,w1)
__device__ int        g_pcount[NSRC * NCELLS];          // pair counts
__device__ float4     g_kc[NCELLS * DCAP];              // stitched kcoefs
__device__ float      g_t0c[NCELLS * DCAP];             // theta0 in stitched order
__device__ int        g_dcountc[NCELLS];
__device__ float      g_part[NB * NCELLS];              // per (b, cell) dot partials

__device__ __forceinline__ int cell_of(float x, float y, float z) {
    int cx = min(NC - 1, max(0, (int)(x * 0.5f)));
    int cy = min(NC - 1, max(0, (int)(y * 0.5f)));
    int cz = min(NC - 1, max(0, (int)(z * 0.5f)));
    return (cz * NC + cy) * NC + cx;
}

// ---- packed f32x2 helpers --------------------------------------------------
__device__ __forceinline__ u64 pk2(float lo, float hi) {
    u64 r; asm("mov.b64 %0, {%1, %2};" : "=l"(r) : "f"(lo), "f"(hi)); return r;
}
__device__ __forceinline__ void upk2(u64 v, float& lo, float& hi) {
    asm("mov.b64 {%0, %1}, %2;" : "=f"(lo), "=f"(hi) : "l"(v));
}
__device__ __forceinline__ u64 fma2(u64 a, u64 b, u64 c) {
    u64 r; asm("fma.rn.f32x2 %0, %1, %2, %3;" : "=l"(r) : "l"(a), "l"(b), "l"(c)); return r;
}
__device__ __forceinline__ u64 add2(u64 a, u64 b) {
    u64 r; asm("add.rn.f32x2 %0, %1, %2;" : "=l"(r) : "l"(a), "l"(b)); return r;
}
__device__ __forceinline__ float ex2(float a) {
    float e; asm("ex2.approx.ftz.f32 %0, %1;" : "=f"(e) : "f"(a)); return e;
}

// inner f32x2 theta accumulator over a pair list in smem -----------------------
__device__ __forceinline__ float theta_point(const float4 kc,
                                             const ulonglong2* __restrict__ sA,
                                             const ulonglong2* __restrict__ sB,
                                             int npairs) {
    const u64 kx2 = pk2(kc.x, kc.x);
    const u64 ky2 = pk2(kc.y, kc.y);
    const u64 kz2 = pk2(kc.z, kc.z);
    const u64 kw2 = pk2(kc.w, kc.w);
    u64 acc = 0ull;
    #pragma unroll 4
    for (int jp = 0; jp < npairs; ++jp) {
        ulonglong2 A = sA[jp];
        ulonglong2 B = sB[jp];
        u64 t = add2(B.y, kw2);
        t = fma2(kz2, B.x, t);
        t = fma2(ky2, A.y, t);
        t = fma2(kx2, A.x, t);
        float lo, hi; upk2(t, lo, hi);
        acc = add2(acc, pk2(ex2(lo), ex2(hi)));
    }
    float a0, a1; upk2(acc, a0, a1);
    return a0 + a1;
}

// ---------------------------------------------------------------------------
// prep1: 16 blocks x 1024 threads — DETERMINISTIC dom binning by slice
// (match_any per-warp counts + parallel across-warp prefix; slot = warp base
// + intra-warp lane rank -> stitched order is run-stable, which the fused dot
// requires). Also writes per-point kcoef (kx, ky, kz, -L*|k|^2).
// ---------------------------------------------------------------------------
__global__ void __launch_bounds__(1024) prep1_kernel(const float* __restrict__ dom) {
    __shared__ int wcnt[32 * 128];           // [warp][cell]
    const int tid = threadIdx.x;
    const int bid = blockIdx.x;
    const int lane = tid & 31;
    const int w    = tid >> 5;

    #pragma unroll
    for (int i = 0; i < 4; ++i) wcnt[tid + i * 1024] = 0;

    const int k = bid * 1024 + tid;
    const float x = dom[k * 3 + 0];
    const float y = dom[k * 3 + 1];
    const float z = dom[k * 3 + 2];
    g_kcoef[k] = make_float4(x, y, z, -LCONST * (x * x + y * y + z * z));
    const int c = cell_of(x, y, z);
    __syncthreads();

    unsigned mm  = __match_any_sync(0xffffffffu, c);
    int     rank = __popc(mm & ((1u << lane) - 1u));
    if (rank == 0) wcnt[w * 128 + c] = __popc(mm);
    __syncthreads();

    if (tid < NCELLS) {
        int acc = 0;
        #pragma unroll
        for (int ww = 0; ww < 32; ++ww) {
            int v = wcnt[ww * 128 + tid];
            wcnt[ww * 128 + tid] = acc;       // exclusive warp base
            acc += v;
        }
        g_dcnt2[tid * NSLICE + bid] = min(acc, SLCAP);
    }
    __syncthreads();

    int slot = wcnt[w * 128 + c] + rank;
    if (slot < SLCAP) g_dslice[(c * NSLICE + bid) * SLCAP + slot] = k;
}

// ---------------------------------------------------------------------------
// prep2: grid (125, 17) x 128 threads. Per (cell, source):
//   load ALL 1024 raw atoms of the source to smem, prune to atoms within
//   distance 2.0 of the home cell cube (dropped terms < 2^-36 each),
//   transform to coefficients, pack f32x2 pairs -> global (and smem).
// s==0 blocks additionally stitch the cell's dom points into contiguous
//   (kcoef) arrays (smem + global) and compute theta0 into g_t0c.
// Deterministic: prune preserves atom index order; theta0 inner order fixed.
// ---------------------------------------------------------------------------
__global__ void __launch_bounds__(128) prep2_kernel(const float* __restrict__ C1,
                                                    const float* __restrict__ C) {
    __shared__ float4     satoms[NATOMS];     // raw coords, then compacted
    __shared__ ulonglong2 sA[NPAIR], sB[NPAIR];
    __shared__ float4     skc[DCAP];
    __shared__ int        sNk, sNpts;
    const int cell = blockIdx.x;
    const int s    = blockIdx.y;
    const int tid  = threadIdx.x;
    const int lane = tid & 31;
    const int cx = cell % NC, cy = (cell / NC) % NC, cz = cell / (NC * NC);

    const float* src = (s == 0) ? C : (C1 + (size_t)(s - 1) * NATOMS * 3);
    for (int i = tid; i < NATOMS; i += 128) {
        satoms[i] = make_float4(src[i * 3 + 0], src[i * 3 + 1], src[i * 3 + 2], 0.f);
    }
    __syncthreads();

    // prune (warp 0, deterministic in-place ballot compaction over all atoms)
    if (tid < 32) {
        const float lox = cx * 2.f, hix = lox + 2.f;
        const float loy = cy * 2.f, hiy = loy + 2.f;
        const float loz = cz * 2.f, hiz = loz + 2.f;
        int nk = 0;
        for (int i0 = 0; i0 < NATOMS; i0 += 32) {
            int i = i0 + lane;
            float4 a = satoms[i];
            float dx = fmaxf(fmaxf(lox - a.x, a.x - hix), 0.f);
            float dy = fmaxf(fmaxf(loy - a.y, a.y - hiy), 0.f);
            float dz = fmaxf(fmaxf(loz - a.z, a.z - hiz), 0.f);
            bool keep = fmaf(dx, dx, fmaf(dy, dy, dz * dz)) <= 4.0f;
            unsigned m = __ballot_sync(0xffffffffu, keep);
            __syncwarp();
            if (keep) {
                int pos = nk + __popc(m & ((1u << lane) - 1u));
                if (pos < SCAP) satoms[pos] = a;
            }
            nk += __popc(m);
        }
        if (lane == 0) sNk = min(nk, SCAP);
    }
    __syncthreads();

    const int nk     = sNk;
    const int npairs = (nk + 1) >> 1;

    // pack coefficient pairs (transform raw -> (2Lx,2Ly,2Lz,-L|x|^2) here)
    ulonglong2* gA = g_pairsA + (size_t)(s * NCELLS + cell) * NPAIR;
    ulonglong2* gB = g_pairsB + (size_t)(s * NCELLS + cell) * NPAIR;
    for (int jp = tid; jp < npairs; jp += 128) {
        float4 a = satoms[2 * jp];
        float4 ac = make_float4(2.f * LCONST * a.x, 2.f * LCONST * a.y,
                                2.f * LCONST * a.z,
                                -LCONST * (a.x * a.x + a.y * a.y + a.z * a.z));
        float4 bc;
        if (2 * jp + 1 < nk) {
            float4 b = satoms[2 * jp + 1];
            bc = make_float4(2.f * LCONST * b.x, 2.f * LCONST * b.y,
                             2.f * LCONST * b.z,
                             -LCONST * (b.x * b.x + b.y * b.y + b.z * b.z));
        } else {
            bc = make_float4(0.f, 0.f, 0.f, -1e30f);   // pad -> exp2 flushes to 0
        }
        ulonglong2 pa = make_ulonglong2(pk2(ac.x, bc.x), pk2(ac.y, bc.y));
        ulonglong2 pb = make_ulonglong2(pk2(ac.z, bc.z), pk2(ac.w, bc.w));
        gA[jp] = pa;  gB[jp] = pb;
        sA[jp] = pa;  sB[jp] = pb;
    }
    if (tid == 0) g_pcount[s * NCELLS + cell] = npairs;

    if (s == 0) {
        // stitch dom points (deterministic order) into smem + global
        __shared__ int scnt16[NSLICE], soff16[NSLICE + 1];
        if (tid < NSLICE) scnt16[tid] = g_dcnt2[cell * NSLICE + tid];
        __syncthreads();
        if (tid == 0) {
            int a = 0;
            #pragma unroll
            for (int i = 0; i < NSLICE; ++i) { soff16[i] = a; a += scnt16[i]; }
            soff16[NSLICE] = a;
            g_dcountc[cell] = a;
            sNpts = a;
        }
        __syncthreads();
        for (int idx = tid; idx < NSLICE * SLCAP; idx += 128) {
            int sl = idx / SLCAP, j = idx % SLCAP;
            if (j < scnt16[sl]) {
                int k = g_dslice[(cell * NSLICE + sl) * SLCAP + j];
                int pos = soff16[sl] + j;
                float4 kc = g_kcoef[k];
                skc[pos] = kc;
                g_kc[cell * DCAP + pos] = kc;
            }
        }
        __syncthreads();

        // theta0 for this cell's points (fixed order)
        const int npts = sNpts;
        for (int p = tid; p < npts; p += 128) {
            g_t0c[cell * DCAP + p] = theta_point(skc[p], sA, sB, npairs);
        }
    }
}

// ---------------------------------------------------------------------------
// thetaB: grid (125, 16) x 160 threads, s = b+1. Computes theta_b per point,
// multiplies by theta0 (stitched order) immediately, and block-reduces to one
// partial per (b, cell). Deterministic: fixed per-thread point order, fixed
// warp-shuffle + cross-warp fold order.
// ---------------------------------------------------------------------------
__global__ void __launch_bounds__(160) thetaB_kernel() {
    __shared__ ulonglong2 sA[NPAIR];
    __shared__ ulonglong2 sB[NPAIR];
    __shared__ float      red[5];
    const int cell = blockIdx.x;
    const int b    = blockIdx.y;
    const int s    = b + 1;
    const int tid  = threadIdx.x;
    const int lane = tid & 31;
    const int w    = tid >> 5;

    const int npairs = g_pcount[s * NCELLS + cell];
    const int npts   = g_dcountc[cell];
    const ulonglong2* gA = g_pairsA + (size_t)(s * NCELLS + cell) * NPAIR;
    const ulonglong2* gB = g_pairsB + (size_t)(s * NCELLS + cell) * NPAIR;
    for (int i = tid; i < npairs; i += 160) {
        sA[i] = gA[i];
        sB[i] = gB[i];
    }
    __syncthreads();

    float pdot = 0.f;
    for (int p = tid; p < npts; p += 160) {
        float tb = theta_point(g_kc[cell * DCAP + p], sA, sB, npairs);
        pdot += tb * g_t0c[cell * DCAP + p];
    }
    #pragma unroll
    for (int st = 16; st > 0; st >>= 1)
        pdot += __shfl_down_sync(0xffffffffu, pdot, st);
    if (lane == 0) red[w] = pdot;
    __syncthreads();
    if (tid == 0) {
        float a = 0.f;
        #pragma unroll
        for (int i = 0; i < 5; ++i) a += red[i];
        g_part[b * NCELLS + cell] = a;
    }
}

// ---------------------------------------------------------------------------
// final: 1 block x 512 threads. 32 threads per b fold the 125 cell partials
// in fixed strided order + shuffle tree. out[b] = 1 - clip(scale*dot, 0, 1),
// scale = A*V/sqrt(n1*n2) = 8 * (1000/16384) / 1024.
// ---------------------------------------------------------------------------
__global__ void __launch_bounds__(512) final_kernel(float* __restrict__ out) {
    const int tid = threadIdx.x;
    const int b = tid >> 5, lane = tid & 31;
    float a = 0.f;
    for (int c = lane; c < NCELLS; c += 32)
        a += g_part[b * NCELLS + c];
    #pragma unroll
    for (int st = 16; st > 0; st >>= 1)
        a += __shfl_down_sync(0xffffffffu, a, st);
    if (lane == 0) {
        float dot = 4.76837158203125e-4f * a;
        dot = fminf(fmaxf(dot, 0.f), 1.f);
        out[b] = 1.f - dot;
    }
}

extern "C" void kernel_launch(void* const* d_in, const int* in_sizes, int n_in,
                              void* d_out, int out_size) {
    const float* C1  = (const float*)d_in[0];   // (16, 1024, 3)
    const float* C   = (const float*)d_in[1];   // (1024, 3)
    const float* dom = (const float*)d_in[2];   // (16384, 3)

    prep1_kernel<<<NSLICE, 1024>>>(dom);
    prep2_kernel<<<dim3(NCELLS, NSRC), 128>>>(C1, C);
    thetaB_kernel<<<dim3(NCELLS, NB), 160>>>();
    final_kernel<<<1, 512>>>((float*)d_out);
}

// round 14
// speedup vs baseline: 1.7488x; 1.1251x over previous
#include <cuda_runtime.h>

#define KPTS    16384
#define NATOMS  1024
#define NB      16
#define NSRC    17      // source 0 = C, sources 1..16 = C1[b]
#define NC      5       // cells per axis (h = 2.0)
#define NCELLS  125
#define NSLICE  16      // dom binning slices (1024 points each)
#define SLCAP   40      // dom points per (cell, slice) capacity (mean 8.2)
#define DCAP    640     // max dom points per cell (16*40)
#define SCAP    256     // pruned atom capacity per cell (mean ~92 @ R=1.4)
#define NPAIR   (SCAP / 2)

// L = inv2s * log2(e) = 2*pi * 1.4426950408889634
#define LCONST  9.064720283654388f
// prune cutoff: atoms farther than RCUT from the cell cube are dropped.
// worst-case truncation ~2e-5 relative per theta (tolerance 1e-3).
#define RCUT2   1.96f   // 1.4^2

typedef unsigned long long u64;

// static scratch (no allocations allowed)
__device__ int        g_dslice[NCELLS * NSLICE * SLCAP];
__device__ int        g_dcnt2[NCELLS * NSLICE];
__device__ float4     g_kcoef[KPTS];
__device__ ulonglong2 g_pairsA[NSRC * NCELLS * NPAIR];  // (x0,x1),(y0,y1)
__device__ ulonglong2 g_pairsB[NSRC * NCELLS * NPAIR];  // (z0,z1),(w0,w1)
__device__ int        g_pcount[NSRC * NCELLS];          // pair counts
__device__ float4     g_kc[NCELLS * DCAP];              // stitched kcoefs
__device__ float      g_t0c[NCELLS * DCAP];             // theta0 in stitched order
__device__ int        g_dcountc[NCELLS];
__device__ float      g_part[NB * NCELLS];              // per (b, cell) dot partials
__device__ int        g_ctr[NB];                        // completion counters (self-resetting)

__device__ __forceinline__ int cell_of(float x, float y, float z) {
    int cx = min(NC - 1, max(0, (int)(x * 0.5f)));
    int cy = min(NC - 1, max(0, (int)(y * 0.5f)));
    int cz = min(NC - 1, max(0, (int)(z * 0.5f)));
    return (cz * NC + cy) * NC + cx;
}

// ---- packed f32x2 helpers --------------------------------------------------
__device__ __forceinline__ u64 pk2(float lo, float hi) {
    u64 r; asm("mov.b64 %0, {%1, %2};" : "=l"(r) : "f"(lo), "f"(hi)); return r;
}
__device__ __forceinline__ void upk2(u64 v, float& lo, float& hi) {
    asm("mov.b64 {%0, %1}, %2;" : "=f"(lo), "=f"(hi) : "l"(v));
}
__device__ __forceinline__ u64 fma2(u64 a, u64 b, u64 c) {
    u64 r; asm("fma.rn.f32x2 %0, %1, %2, %3;" : "=l"(r) : "l"(a), "l"(b), "l"(c)); return r;
}
__device__ __forceinline__ u64 add2(u64 a, u64 b) {
    u64 r; asm("add.rn.f32x2 %0, %1, %2;" : "=l"(r) : "l"(a), "l"(b)); return r;
}
__device__ __forceinline__ float ex2(float a) {
    float e; asm("ex2.approx.ftz.f32 %0, %1;" : "=f"(e) : "f"(a)); return e;
}
__device__ __forceinline__ float ldcg(const float* p) {
    float v; asm volatile("ld.global.cg.f32 %0, [%1];" : "=f"(v) : "l"(p)); return v;
}

// inner f32x2 theta accumulator over a pair list in smem ----------------------
__device__ __forceinline__ float theta_point(const float4 kc,
                                             const ulonglong2* __restrict__ sA,
                                             const ulonglong2* __restrict__ sB,
                                             int npairs) {
    const u64 kx2 = pk2(kc.x, kc.x);
    const u64 ky2 = pk2(kc.y, kc.y);
    const u64 kz2 = pk2(kc.z, kc.z);
    const u64 kw2 = pk2(kc.w, kc.w);
    u64 acc = 0ull;
    #pragma unroll 4
    for (int jp = 0; jp < npairs; ++jp) {
        ulonglong2 A = sA[jp];
        ulonglong2 B = sB[jp];
        u64 t = add2(B.y, kw2);
        t = fma2(kz2, B.x, t);
        t = fma2(ky2, A.y, t);
        t = fma2(kx2, A.x, t);
        float lo, hi; upk2(t, lo, hi);
        acc = add2(acc, pk2(ex2(lo), ex2(hi)));
    }
    float a0, a1; upk2(acc, a0, a1);
    return a0 + a1;
}

// ---------------------------------------------------------------------------
// prep1: 16 blocks x 1024 threads — DETERMINISTIC dom binning by slice
// (match_any per-warp counts + parallel across-warp prefix; slot = warp base
// + intra-warp lane rank -> stitched order is run-stable, which the fused dot
// requires). Also writes per-point kcoef (kx, ky, kz, -L*|k|^2).
// ---------------------------------------------------------------------------
__global__ void __launch_bounds__(1024) prep1_kernel(const float* __restrict__ dom) {
    __shared__ int wcnt[32 * 128];           // [warp][cell]
    const int tid = threadIdx.x;
    const int bid = blockIdx.x;
    const int lane = tid & 31;
    const int w    = tid >> 5;

    #pragma unroll
    for (int i = 0; i < 4; ++i) wcnt[tid + i * 1024] = 0;

    const int k = bid * 1024 + tid;
    const float x = dom[k * 3 + 0];
    const float y = dom[k * 3 + 1];
    const float z = dom[k * 3 + 2];
    g_kcoef[k] = make_float4(x, y, z, -LCONST * (x * x + y * y + z * z));
    const int c = cell_of(x, y, z);
    __syncthreads();

    unsigned mm  = __match_any_sync(0xffffffffu, c);
    int     rank = __popc(mm & ((1u << lane) - 1u));
    if (rank == 0) wcnt[w * 128 + c] = __popc(mm);
    __syncthreads();

    if (tid < NCELLS) {
        int acc = 0;
        #pragma unroll
        for (int ww = 0; ww < 32; ++ww) {
            int v = wcnt[ww * 128 + tid];
            wcnt[ww * 128 + tid] = acc;       // exclusive warp base
            acc += v;
        }
        g_dcnt2[tid * NSLICE + bid] = min(acc, SLCAP);
    }
    __syncthreads();

    int slot = wcnt[w * 128 + c] + rank;
    if (slot < SLCAP) g_dslice[(c * NSLICE + bid) * SLCAP + slot] = k;
}

// ---------------------------------------------------------------------------
// prep2: grid (125, 17) x 128 threads. Per (cell, source):
//   load ALL 1024 raw atoms of the source to smem, prune to atoms within
//   RCUT of the home cell cube (dropped terms bounded above), transform to
//   coefficients, pack f32x2 pairs -> global (and smem).
// s==0 blocks additionally stitch the cell's dom points into contiguous
//   (kcoef) arrays (smem + global) and compute theta0 into g_t0c.
// Deterministic: prune preserves atom index order; theta0 inner order fixed.
// ---------------------------------------------------------------------------
__global__ void __launch_bounds__(128) prep2_kernel(const float* __restrict__ C1,
                                                    const float* __restrict__ C) {
    __shared__ float4     satoms[NATOMS];     // raw coords, then compacted
    __shared__ ulonglong2 sA[NPAIR], sB[NPAIR];
    __shared__ float4     skc[DCAP];
    __shared__ int        sNk, sNpts;
    const int cell = blockIdx.x;
    const int s    = blockIdx.y;
    const int tid  = threadIdx.x;
    const int lane = tid & 31;
    const int cx = cell % NC, cy = (cell / NC) % NC, cz = cell / (NC * NC);

    const float* src = (s == 0) ? C : (C1 + (size_t)(s - 1) * NATOMS * 3);
    for (int i = tid; i < NATOMS; i += 128) {
        satoms[i] = make_float4(src[i * 3 + 0], src[i * 3 + 1], src[i * 3 + 2], 0.f);
    }
    __syncthreads();

    // prune (warp 0, deterministic in-place ballot compaction over all atoms)
    if (tid < 32) {
        const float lox = cx * 2.f, hix = lox + 2.f;
        const float loy = cy * 2.f, hiy = loy + 2.f;
        const float loz = cz * 2.f, hiz = loz + 2.f;
        int nk = 0;
        for (int i0 = 0; i0 < NATOMS; i0 += 32) {
            int i = i0 + lane;
            float4 a = satoms[i];
            float dx = fmaxf(fmaxf(lox - a.x, a.x - hix), 0.f);
            float dy = fmaxf(fmaxf(loy - a.y, a.y - hiy), 0.f);
            float dz = fmaxf(fmaxf(loz - a.z, a.z - hiz), 0.f);
            bool keep = fmaf(dx, dx, fmaf(dy, dy, dz * dz)) <= RCUT2;
            unsigned m = __ballot_sync(0xffffffffu, keep);
            __syncwarp();
            if (keep) {
                int pos = nk + __popc(m & ((1u << lane) - 1u));
                if (pos < SCAP) satoms[pos] = a;
            }
            nk += __popc(m);
        }
        if (lane == 0) sNk = min(nk, SCAP);
    }
    __syncthreads();

    const int nk     = sNk;
    const int npairs = (nk + 1) >> 1;

    // pack coefficient pairs (transform raw -> (2Lx,2Ly,2Lz,-L|x|^2) here)
    ulonglong2* gA = g_pairsA + (size_t)(s * NCELLS + cell) * NPAIR;
    ulonglong2* gB = g_pairsB + (size_t)(s * NCELLS + cell) * NPAIR;
    for (int jp = tid; jp < npairs; jp += 128) {
        float4 a = satoms[2 * jp];
        float4 ac = make_float4(2.f * LCONST * a.x, 2.f * LCONST * a.y,
                                2.f * LCONST * a.z,
                                -LCONST * (a.x * a.x + a.y * a.y + a.z * a.z));
        float4 bc;
        if (2 * jp + 1 < nk) {
            float4 b = satoms[2 * jp + 1];
            bc = make_float4(2.f * LCONST * b.x, 2.f * LCONST * b.y,
                             2.f * LCONST * b.z,
                             -LCONST * (b.x * b.x + b.y * b.y + b.z * b.z));
        } else {
            bc = make_float4(0.f, 0.f, 0.f, -1e30f);   // pad -> exp2 flushes to 0
        }
        ulonglong2 pa = make_ulonglong2(pk2(ac.x, bc.x), pk2(ac.y, bc.y));
        ulonglong2 pb = make_ulonglong2(pk2(ac.z, bc.z), pk2(ac.w, bc.w));
        gA[jp] = pa;  gB[jp] = pb;
        sA[jp] = pa;  sB[jp] = pb;
    }
    if (tid == 0) g_pcount[s * NCELLS + cell] = npairs;

    if (s == 0) {
        // stitch dom points (deterministic order) into smem + global
        __shared__ int scnt16[NSLICE], soff16[NSLICE + 1];
        if (tid < NSLICE) scnt16[tid] = g_dcnt2[cell * NSLICE + tid];
        __syncthreads();
        if (tid == 0) {
            int a = 0;
            #pragma unroll
            for (int i = 0; i < NSLICE; ++i) { soff16[i] = a; a += scnt16[i]; }
            soff16[NSLICE] = a;
            g_dcountc[cell] = a;
            sNpts = a;
        }
        __syncthreads();
        for (int idx = tid; idx < NSLICE * SLCAP; idx += 128) {
            int sl = idx / SLCAP, j = idx % SLCAP;
            if (j < scnt16[sl]) {
                int k = g_dslice[(cell * NSLICE + sl) * SLCAP + j];
                int pos = soff16[sl] + j;
                float4 kc = g_kcoef[k];
                skc[pos] = kc;
                g_kc[cell * DCAP + pos] = kc;
            }
        }
        __syncthreads();

        // theta0 for this cell's points (fixed order)
        const int npts = sNpts;
        for (int p = tid; p < npts; p += 128) {
            g_t0c[cell * DCAP + p] = theta_point(skc[p], sA, sB, npairs);
        }
    }
}

// ---------------------------------------------------------------------------
// thetaB: grid (125, 16) x 160 threads, s = b+1. Computes theta_b per point,
// multiplies by theta0 (stitched order) immediately, block-reduces to one
// partial per (b, cell). The LAST block per b (elected by atomic counter)
// folds all 125 partials IN FIXED ORDER and writes out[b], then resets the
// counter for graph replay. Deterministic: the atomic elects only WHO folds;
// the fold order is fixed.
// scale = A*V/sqrt(n1*n2) = 8 * (1000/16384) / 1024.
// ---------------------------------------------------------------------------
__global__ void __launch_bounds__(160) thetaB_kernel(float* __restrict__ out) {
    __shared__ ulonglong2 sA[NPAIR];
    __shared__ ulonglong2 sB[NPAIR];
    __shared__ float      red[5];
    __shared__ int        sIsLast;
    const int cell = blockIdx.x;
    const int b    = blockIdx.y;
    const int s    = b + 1;
    const int tid  = threadIdx.x;
    const int lane = tid & 31;
    const int w    = tid >> 5;

    const int npairs = g_pcount[s * NCELLS + cell];
    const int npts   = g_dcountc[cell];
    const ulonglong2* gA = g_pairsA + (size_t)(s * NCELLS + cell) * NPAIR;
    const ulonglong2* gB = g_pairsB + (size_t)(s * NCELLS + cell) * NPAIR;
    for (int i = tid; i < npairs; i += 160) {
        sA[i] = gA[i];
        sB[i] = gB[i];
    }
    __syncthreads();

    float pdot = 0.f;
    for (int p = tid; p < npts; p += 160) {
        float tb = theta_point(g_kc[cell * DCAP + p], sA, sB, npairs);
        pdot += tb * g_t0c[cell * DCAP + p];
    }
    #pragma unroll
    for (int st = 16; st > 0; st >>= 1)
        pdot += __shfl_down_sync(0xffffffffu, pdot, st);
    if (lane == 0) red[w] = pdot;
    __syncthreads();
    if (tid == 0) {
        float a = 0.f;
        #pragma unroll
        for (int i = 0; i < 5; ++i) a += red[i];
        g_part[b * NCELLS + cell] = a;
        __threadfence();
        int old = atomicAdd(&g_ctr[b], 1);
        sIsLast = (old == NCELLS - 1);
    }
    __syncthreads();

    if (sIsLast) {
        __threadfence();
        // fold 125 partials in fixed order (warps 0..3, lanes ascending)
        float v = (tid < NCELLS) ? ldcg(&g_part[b * NCELLS + tid]) : 0.f;
        #pragma unroll
        for (int st = 16; st > 0; st >>= 1)
            v += __shfl_down_sync(0xffffffffu, v, st);
        if (lane == 0) red[w] = v;
        __syncthreads();
        if (tid == 0) {
            float a = ((red[0] + red[1]) + (red[2] + red[3])) + red[4];
            float dot = 4.76837158203125e-4f * a;
            dot = fminf(fmaxf(dot, 0.f), 1.f);
            out[b] = 1.f - dot;
            g_ctr[b] = 0;                    // reset for graph replay
        }
    }
}

extern "C" void kernel_launch(void* const* d_in, const int* in_sizes, int n_in,
                              void* d_out, int out_size) {
    const float* C1  = (const float*)d_in[0];   // (16, 1024, 3)
    const float* C   = (const float*)d_in[1];   // (1024, 3)
    const float* dom = (const float*)d_in[2];   // (16384, 3)

    prep1_kernel<<<NSLICE, 1024>>>(dom);
    prep2_kernel<<<dim3(NCELLS, NSRC), 128>>>(C1, C);
    thetaB_kernel<<<dim3(NCELLS, NB), 160>>>((float*)d_out);
}